// round 16
// baseline (speedup 1.0000x reference)
#include <cuda_runtime.h>
#include <cuda_fp16.h>
#include <cstdint>

#define SEQ  2048
#define WORD 1024
#define EMB  128
#define NH   16
#define NSPLIT 8
#define HK   (NH * EMB)            /* 2048 */
#define QSC  0.1275174405080890f   /* (1/sqrt(128)) * log2(e) */

// ---------------- device scratch (no allocations allowed) ----------------
__device__ float g_Pp[NSPLIT * SEQ * EMB];    // proj split-K partials

// all operands single fp16 (1-term scheme)
__device__ __align__(16) __half g_x  [SEQ * WORD];
__device__ __align__(16) __half g_W  [48 * WORD * EMB];   // [z][w][e]
__device__ __align__(16) __half g_Q  [NH * SEQ * EMB];    // scaled by QSC
__device__ __align__(16) __half g_K  [NH * SEQ * EMB];
__device__ __align__(16) __half g_V  [NH * SEQ * EMB];
__device__ __align__(16) __half g_Z  [SEQ * HK];          // [s][h*EMB+e]
__device__ __align__(16) __half g_P  [HK * EMB];          // proj

// ---------------- helpers ----------------
__device__ __forceinline__ float ex2f_(float x) {
    float y; asm("ex2.approx.ftz.f32 %0, %1;" : "=f"(y) : "f"(x)); return y;
}
__device__ __forceinline__ void mma16816(float* c, const uint32_t* a, uint32_t b0, uint32_t b1) {
    asm volatile(
        "mma.sync.aligned.m16n8k16.row.col.f32.f16.f16.f32 "
        "{%0,%1,%2,%3}, {%4,%5,%6,%7}, {%8,%9}, {%0,%1,%2,%3};"
        : "+f"(c[0]), "+f"(c[1]), "+f"(c[2]), "+f"(c[3])
        : "r"(a[0]), "r"(a[1]), "r"(a[2]), "r"(a[3]), "r"(b0), "r"(b1));
}
// fp16-accumulator variant: D/C are 2 b32 regs (4 halves)
__device__ __forceinline__ void mma16816h(uint32_t* d, const uint32_t* a, uint32_t b0, uint32_t b1) {
    asm volatile(
        "mma.sync.aligned.m16n8k16.row.col.f16.f16.f16.f16 "
        "{%0,%1}, {%2,%3,%4,%5}, {%6,%7}, {%0,%1};"
        : "+r"(d[0]), "+r"(d[1])
        : "r"(a[0]), "r"(a[1]), "r"(a[2]), "r"(a[3]), "r"(b0), "r"(b1));
}
#define LDSM4(R, addr) \
    asm volatile("ldmatrix.sync.aligned.m8n8.x4.shared.b16 {%0,%1,%2,%3}, [%4];" \
        : "=r"((R)[0]), "=r"((R)[1]), "=r"((R)[2]), "=r"((R)[3]) : "r"(addr))
#define LDSM4T(R, addr) \
    asm volatile("ldmatrix.sync.aligned.m8n8.x4.trans.shared.b16 {%0,%1,%2,%3}, [%4];" \
        : "=r"((R)[0]), "=r"((R)[1]), "=r"((R)[2]), "=r"((R)[3]) : "r"(addr))
__device__ __forceinline__ void cpa(uint32_t dst, const void* src) {
    asm volatile("cp.async.cg.shared.global [%0], [%1], 16;" :: "r"(dst), "l"(src));
}
#define CP_COMMIT() asm volatile("cp.async.commit_group;")
__device__ __forceinline__ uint32_t smem_u32(const void* p) {
    uint32_t a;
    asm("{ .reg .u64 t; cvta.to.shared.u64 t, %1; cvt.u32.u64 %0, t; }" : "=r"(a) : "l"(p));
    return a;
}
__device__ __forceinline__ uint32_t pkh(__half a, __half b) {
    uint16_t ua = *(uint16_t*)&a, ub = *(uint16_t*)&b;
    return (uint32_t)ua | ((uint32_t)ub << 16);
}

// =======================================================================
// conv_all: fused fp32 -> fp16 conversion for x, W(q|k|v), proj.
//   grid 8448 x 256, 4 elems/thread.
// =======================================================================
#define NX (SEQ * WORD)          /* 2097152 */
#define NW (48 * WORD * EMB)     /* 6291456 */
#define NP (HK * EMB)            /*  262144 */

__global__ __launch_bounds__(256)
void conv_all(const float* __restrict__ x,
              const float* __restrict__ Wq, const float* __restrict__ Wk,
              const float* __restrict__ Wv, const float* __restrict__ proj)
{
    int i = (blockIdx.x * 256 + threadIdx.x) * 4;
    const float* src;
    __half* dst;
    int off;
    if (i < NX) {
        src = x; dst = g_x; off = i;
    } else if (i < NX + NW) {
        int idx = i - NX;
        const int WE = WORD * EMB;
        int z = idx / WE;
        int zo = idx - z * WE;
        const float* W = (z < 16 ? Wq : (z < 32 ? Wk : Wv));
        int hh = (z < 16 ? z : (z < 32 ? z - 16 : z - 32));
        float4 v = *(const float4*)&W[hh * WE + zo];
        *(uint2*)&g_W[idx] = make_uint2(pkh(__float2half_rn(v.x), __float2half_rn(v.y)),
                                        pkh(__float2half_rn(v.z), __float2half_rn(v.w)));
        return;
    } else {
        src = proj; dst = g_P; off = i - NX - NW;
        i = off;
        float4 v = *(const float4*)&src[off];
        *(uint2*)&dst[off] = make_uint2(pkh(__float2half_rn(v.x), __float2half_rn(v.y)),
                                        pkh(__float2half_rn(v.z), __float2half_rn(v.w)));
        return;
    }
    float4 v = *(const float4*)&src[off];
    *(uint2*)&dst[off] = make_uint2(pkh(__float2half_rn(v.x), __float2half_rn(v.y)),
                                    pkh(__float2half_rn(v.z), __float2half_rn(v.w)));
}

// =======================================================================
// gemm_qkv_mma: 1-term fp16 HMMA GEMM (unchanged from R15 best).
// =======================================================================
#define XT_SZ  18432                 /* 128 x 72 fp16 (144B rows) */
#define WT_SZ  17408                 /* 64 x 136 fp16 (272B rows) */
#define QKV_BUF (XT_SZ + WT_SZ)      /* 35840 */
#define QKV_SMEM3 (3*QKV_BUF)        /* 107520 */
#define PRJ_SMEM  (2*QKV_BUF)        /* 71680 */

__global__ __launch_bounds__(256, 2)
void gemm_qkv_mma(const float* __restrict__ bq, const float* __restrict__ bk,
                  const float* __restrict__ bv)
{
    extern __shared__ char smem[];
    const uint32_t sb = smem_u32(smem);
    const int tid = threadIdx.x, w = tid >> 5, lane = tid & 31;
    const int z = blockIdx.y, kind = z >> 4, h = z & 15;
    const int row0 = blockIdx.x * 128;
    const float* bp = (kind == 0 ? bq : (kind == 1 ? bk : bv)) + h * EMB;
    const int wr = w >> 1, wc = w & 1;          // 4 row-groups x 2 col-groups

    const __half* xp = g_x + (size_t)row0 * WORD;
    const __half* wp = g_W + (size_t)z * WORD * EMB;

    auto issue = [&](int kt) {
        uint32_t b = sb + (kt % 3) * QKV_BUF;
        int k0 = kt * 64;
#pragma unroll
        for (int t = 0; t < 4; t++) {                  // x tile [128][64]
            int idx = tid + t * 256;
            int r = idx >> 3, s = idx & 7;
            cpa(b + r * 144 + s * 16, xp + r * WORD + k0 + s * 8);
        }
#pragma unroll
        for (int t = 0; t < 4; t++) {                  // W tile [64][128]
            int idx = tid + t * 256;
            int r = idx >> 4, s = idx & 15;
            cpa(b + XT_SZ + r * 272 + s * 16, wp + (k0 + r) * EMB + s * 8);
        }
        CP_COMMIT();
    };
    issue(0); issue(1);

    float c[2][8][4];
#pragma unroll
    for (int rt = 0; rt < 2; rt++)
#pragma unroll
        for (int j = 0; j < 8; j++)
#pragma unroll
            for (int p = 0; p < 4; p++) c[rt][j][p] = 0.f;

    const int g = lane >> 2, t4 = lane & 3;
    const uint32_t a_off = (uint32_t)((wr * 32 + (lane & 15)) * 144 + (lane >> 4) * 16);
    const uint32_t b_off = (uint32_t)(XT_SZ +
        (((lane >> 3) & 1) * 8 + (lane & 7)) * 272 + wc * 128 + (lane >> 4) * 16);

#pragma unroll 1
    for (int kt = 0; kt < 16; kt++) {
        if (kt < 15) asm volatile("cp.async.wait_group 1;");
        else         asm volatile("cp.async.wait_group 0;");
        __syncthreads();                           // buf (kt+2)%3 free
        if (kt + 2 < 16) issue(kt + 2);
        const uint32_t xb = sb + (kt % 3) * QKV_BUF;

#pragma unroll
        for (int kk = 0; kk < 4; kk++) {
            uint32_t ah[2][4];
#pragma unroll
            for (int rt = 0; rt < 2; rt++)
                LDSM4(ah[rt], xb + a_off + rt * 16 * 144 + kk * 32);
#pragma unroll
            for (int np = 0; np < 4; np++) {
                uint32_t ba = xb + b_off + kk * 16 * 272 + np * 32;
                uint32_t bh[4];
                LDSM4T(bh, ba);
#pragma unroll
                for (int rt = 0; rt < 2; rt++) {
                    mma16816(c[rt][2 * np],     ah[rt], bh[0], bh[1]);
                    mma16816(c[rt][2 * np + 1], ah[rt], bh[2], bh[3]);
                }
            }
        }
    }

    // ---- epilogue: bias; Q scaled; all -> single fp16 ----
    const float sc = (kind == 0) ? QSC : 1.0f;
    __half* dd = (kind == 0 ? g_Q : (kind == 1 ? g_K : g_V)) + (size_t)h * SEQ * EMB;
#pragma unroll
    for (int rt = 0; rt < 2; rt++) {
        const int r0 = row0 + wr * 32 + rt * 16 + g, r1 = r0 + 8;
#pragma unroll
        for (int j = 0; j < 8; j++) {
            int col = wc * 64 + 8 * j + 2 * t4;
            float b0 = __ldg(&bp[col]), b1 = __ldg(&bp[col + 1]);
            float v00 = (c[rt][j][0] + b0) * sc, v01 = (c[rt][j][1] + b1) * sc;
            float v10 = (c[rt][j][2] + b0) * sc, v11 = (c[rt][j][3] + b1) * sc;
            *(uint32_t*)&dd[r0 * EMB + col] = pkh(__float2half_rn(v00), __float2half_rn(v01));
            *(uint32_t*)&dd[r1 * EMB + col] = pkh(__float2half_rn(v10), __float2half_rn(v11));
        }
    }
}

// =======================================================================
// attn_mma: FA2 flash attention, 1-term fp16.
//   S: fp32 accum. PV: per-chunk fp16 accum (np-outer), upconverted to
//   fp32 o[] after each chunk's 4-mma chain.
// =======================================================================
#define KT_SZ  17408                  /* 64 x 136 fp16 */
#define AT_BUF (2*KT_SZ)              /* 34816: K | V */
#define QT_SZ  34816                  /* 128 x 136 fp16 */
#define ATT_SMEM (3*AT_BUF + QT_SZ)   /* 139264 */

__global__ __launch_bounds__(256, 1)
void attn_mma()
{
    extern __shared__ char smem[];
    const uint32_t sb = smem_u32(smem);
    const int tid = threadIdx.x, w = tid >> 5, lane = tid & 31;
    const int qb = blockIdx.x * 128, h = blockIdx.y;

    const __half* Qp = g_Q + (size_t)h * SEQ * EMB + (size_t)qb * EMB;
    const __half* Kp = g_K + (size_t)h * SEQ * EMB;
    const __half* Vp = g_V + (size_t)h * SEQ * EMB;

    const uint32_t qbase = sb + 3 * AT_BUF;
#pragma unroll
    for (int t = 0; t < 8; t++) {
        int idx = tid + t * 256;
        int r = idx >> 4, s = idx & 15;
        cpa(qbase + r * 272 + s * 16, Qp + r * EMB + s * 8);
    }
    CP_COMMIT();

    auto issue = [&](int kt) {
        uint32_t b = sb + (kt % 3) * AT_BUF;
        int kb = kt * 64;
#pragma unroll
        for (int t = 0; t < 4; t++) {
            int idx = tid + t * 256;
            int r = idx >> 4, s = idx & 15;
            uint32_t d = b + r * 272 + s * 16;
            const int go = (kb + r) * EMB + s * 8;
            cpa(d,         Kp + go);
            cpa(d + KT_SZ, Vp + go);
        }
        CP_COMMIT();
    };
    issue(0); issue(1);

    asm volatile("cp.async.wait_group 2;");   // Q arrived
    __syncthreads();

    uint32_t qah[8][4];
    const uint32_t qa_off = (uint32_t)((w * 16 + (lane & 15)) * 272 + (lane >> 4) * 16);
#pragma unroll
    for (int kk = 0; kk < 8; kk++)
        LDSM4(qah[kk], qbase + qa_off + kk * 32);

    float o[16][4];
#pragma unroll
    for (int j = 0; j < 16; j++)
#pragma unroll
        for (int p = 0; p < 4; p++) o[j][p] = 0.f;
    float mrow0 = -1e30f, mrow1 = -1e30f, lrow0 = 0.f, lrow1 = 0.f;

    const int g = lane >> 2, t4 = lane & 3;
    const uint32_t kb_row = (uint32_t)(((lane >> 4) << 3) + (lane & 7));
    const uint32_t kb_cadd = (uint32_t)(((lane >> 3) & 1) * 16);
    const uint32_t vb_row = (uint32_t)((((lane >> 3) & 1) * 8) + (lane & 7));
    const uint32_t vb_cadd = (uint32_t)((lane >> 4) * 16);

#pragma unroll 1
    for (int kt = 0; kt < 32; kt++) {
        if (kt < 31) asm volatile("cp.async.wait_group 1;");
        else         asm volatile("cp.async.wait_group 0;");
        __syncthreads();
        if (kt + 2 < 32) issue(kt + 2);
        const uint32_t kbuf = sb + (kt % 3) * AT_BUF;

        // ---- S = Q @ K^T  (fp32 accum, 64 mmas) ----
        float s[8][4];
#pragma unroll
        for (int j = 0; j < 8; j++)
#pragma unroll
            for (int p = 0; p < 4; p++) s[j][p] = 0.f;
#pragma unroll
        for (int kk = 0; kk < 8; kk++) {
#pragma unroll
            for (int np = 0; np < 4; np++) {
                uint32_t ba = kbuf + (np * 16 + kb_row) * 272 + kk * 32 + kb_cadd;
                uint32_t bh[4];
                LDSM4(bh, ba);
                mma16816(s[2 * np],     qah[kk], bh[0], bh[1]);
                mma16816(s[2 * np + 1], qah[kk], bh[2], bh[3]);
            }
        }

        // ---- online softmax ----
        float mx0 = -1e30f, mx1 = -1e30f;
#pragma unroll
        for (int j = 0; j < 8; j++) {
            mx0 = fmaxf(mx0, fmaxf(s[j][0], s[j][1]));
            mx1 = fmaxf(mx1, fmaxf(s[j][2], s[j][3]));
        }
        mx0 = fmaxf(mx0, __shfl_xor_sync(0xffffffffu, mx0, 1));
        mx0 = fmaxf(mx0, __shfl_xor_sync(0xffffffffu, mx0, 2));
        mx1 = fmaxf(mx1, __shfl_xor_sync(0xffffffffu, mx1, 1));
        mx1 = fmaxf(mx1, __shfl_xor_sync(0xffffffffu, mx1, 2));
        float mn0 = fmaxf(mrow0, mx0), mn1 = fmaxf(mrow1, mx1);
        float al0 = ex2f_(mrow0 - mn0), al1 = ex2f_(mrow1 - mn1);
        float rs0 = 0.f, rs1 = 0.f;
#pragma unroll
        for (int j = 0; j < 8; j++) {
            s[j][0] = ex2f_(s[j][0] - mn0);
            s[j][1] = ex2f_(s[j][1] - mn0);
            s[j][2] = ex2f_(s[j][2] - mn1);
            s[j][3] = ex2f_(s[j][3] - mn1);
            rs0 += s[j][0] + s[j][1];
            rs1 += s[j][2] + s[j][3];
        }
        rs0 += __shfl_xor_sync(0xffffffffu, rs0, 1);
        rs0 += __shfl_xor_sync(0xffffffffu, rs0, 2);
        rs1 += __shfl_xor_sync(0xffffffffu, rs1, 1);
        rs1 += __shfl_xor_sync(0xffffffffu, rs1, 2);
        lrow0 = lrow0 * al0 + rs0; mrow0 = mn0;
        lrow1 = lrow1 * al1 + rs1; mrow1 = mn1;
#pragma unroll
        for (int j = 0; j < 16; j++) {
            o[j][0] *= al0; o[j][1] *= al0; o[j][2] *= al1; o[j][3] *= al1;
        }

        // ---- build all P fragments (s dead after this) ----
        uint32_t pah[4][4];
#pragma unroll
        for (int kk = 0; kk < 4; kk++) {
            pah[kk][0] = pkh(__float2half_rn(s[2 * kk][0]),     __float2half_rn(s[2 * kk][1]));
            pah[kk][1] = pkh(__float2half_rn(s[2 * kk][2]),     __float2half_rn(s[2 * kk][3]));
            pah[kk][2] = pkh(__float2half_rn(s[2 * kk + 1][0]), __float2half_rn(s[2 * kk + 1][1]));
            pah[kk][3] = pkh(__float2half_rn(s[2 * kk + 1][2]), __float2half_rn(s[2 * kk + 1][3]));
        }

        // ---- O += P @ V : per-np fp16 accum chain over kk, then upconvert ----
        const uint32_t vbuf = kbuf + KT_SZ;
#pragma unroll
        for (int np = 0; np < 8; np++) {
            uint32_t oh0[2] = {0u, 0u};   // j = 2np   (4 halves)
            uint32_t oh1[2] = {0u, 0u};   // j = 2np+1
#pragma unroll
            for (int kk = 0; kk < 4; kk++) {
                uint32_t va = vbuf + (kk * 16 + vb_row) * 272 + np * 32 + vb_cadd;
                uint32_t vh4[4];
                LDSM4T(vh4, va);
                mma16816h(oh0, pah[kk], vh4[0], vh4[1]);
                mma16816h(oh1, pah[kk], vh4[2], vh4[3]);
            }
            __half2 a0 = *(__half2*)&oh0[0], a1 = *(__half2*)&oh0[1];
            __half2 b0 = *(__half2*)&oh1[0], b1 = *(__half2*)&oh1[1];
            o[2 * np][0] += __half2float(a0.x); o[2 * np][1] += __half2float(a0.y);
            o[2 * np][2] += __half2float(a1.x); o[2 * np][3] += __half2float(a1.y);
            o[2 * np + 1][0] += __half2float(b0.x); o[2 * np + 1][1] += __half2float(b0.y);
            o[2 * np + 1][2] += __half2float(b1.x); o[2 * np + 1][3] += __half2float(b1.y);
        }
    }

    // ---- epilogue: normalize -> single fp16 Z ----
    const float rl0 = 1.0f / lrow0, rl1 = 1.0f / lrow1;
    const int r0 = qb + w * 16 + g, r1 = r0 + 8;
    __half* Z0 = g_Z + (size_t)r0 * HK + h * EMB;
    __half* Z1 = g_Z + (size_t)r1 * HK + h * EMB;
#pragma unroll
    for (int j = 0; j < 16; j++) {
        int col = 8 * j + 2 * t4;
        *(uint32_t*)&Z0[col] = pkh(__float2half_rn(o[j][0] * rl0), __float2half_rn(o[j][1] * rl0));
        *(uint32_t*)&Z1[col] = pkh(__float2half_rn(o[j][2] * rl1), __float2half_rn(o[j][3] * rl1));
    }
}

// =======================================================================
// gemm_proj_mma: split-K proj, 1-term fp16, 2-stage (unchanged).
// =======================================================================
__global__ __launch_bounds__(256, 2)
void gemm_proj_mma()
{
    extern __shared__ char smem[];
    const uint32_t sb = smem_u32(smem);
    const int tid = threadIdx.x, w = tid >> 5, lane = tid & 31;
    const int row0 = blockIdx.x * 128;
    const int ks   = blockIdx.y;
    const int wr = w >> 1, wc = w & 1;

    const __half* zp = g_Z + (size_t)row0 * HK + ks * 256;
    const __half* pp = g_P + (size_t)ks * 256 * EMB;

    auto issue = [&](int kt) {
        uint32_t b = sb + (kt & 1) * QKV_BUF;
        int k0 = kt * 64;
#pragma unroll
        for (int t = 0; t < 4; t++) {
            int idx = tid + t * 256;
            int r = idx >> 3, s = idx & 7;
            cpa(b + r * 144 + s * 16, zp + r * HK + k0 + s * 8);
        }
#pragma unroll
        for (int t = 0; t < 4; t++) {
            int idx = tid + t * 256;
            int r = idx >> 4, s = idx & 15;
            cpa(b + XT_SZ + r * 272 + s * 16, pp + (k0 + r) * EMB + s * 8);
        }
        CP_COMMIT();
    };
    issue(0); issue(1);

    float c[2][8][4];
#pragma unroll
    for (int rt = 0; rt < 2; rt++)
#pragma unroll
        for (int j = 0; j < 8; j++)
#pragma unroll
            for (int p = 0; p < 4; p++) c[rt][j][p] = 0.f;

    const int g = lane >> 2, t4 = lane & 3;
    const uint32_t a_off = (uint32_t)((wr * 32 + (lane & 15)) * 144 + (lane >> 4) * 16);
    const uint32_t b_off = (uint32_t)(XT_SZ +
        (((lane >> 3) & 1) * 8 + (lane & 7)) * 272 + wc * 128 + (lane >> 4) * 16);

#pragma unroll 1
    for (int kt = 0; kt < 4; kt++) {
        if (kt < 3) asm volatile("cp.async.wait_group 1;");
        else        asm volatile("cp.async.wait_group 0;");
        __syncthreads();
        const uint32_t xb = sb + (kt & 1) * QKV_BUF;

#pragma unroll
        for (int kk = 0; kk < 4; kk++) {
            uint32_t ah[2][4];
#pragma unroll
            for (int rt = 0; rt < 2; rt++)
                LDSM4(ah[rt], xb + a_off + rt * 16 * 144 + kk * 32);
#pragma unroll
            for (int np = 0; np < 4; np++) {
                uint32_t ba = xb + b_off + kk * 16 * 272 + np * 32;
                uint32_t bh[4];
                LDSM4T(bh, ba);
#pragma unroll
                for (int rt = 0; rt < 2; rt++) {
                    mma16816(c[rt][2 * np],     ah[rt], bh[0], bh[1]);
                    mma16816(c[rt][2 * np + 1], ah[rt], bh[2], bh[3]);
                }
            }
        }
        __syncthreads();
        if (kt + 2 < 4) issue(kt + 2);
    }

    float* Pp = g_Pp + (size_t)blockIdx.y * SEQ * EMB;
#pragma unroll
    for (int rt = 0; rt < 2; rt++) {
        const int r0 = row0 + wr * 32 + rt * 16 + g, r1 = r0 + 8;
#pragma unroll
        for (int j = 0; j < 8; j++) {
            int col = wc * 64 + 8 * j + 2 * t4;
            *(float2*)&Pp[r0 * EMB + col] = make_float2(c[rt][j][0], c[rt][j][1]);
            *(float2*)&Pp[r1 * EMB + col] = make_float2(c[rt][j][2], c[rt][j][3]);
        }
    }
}

__global__ __launch_bounds__(256)
void proj_reduce(float* __restrict__ out)
{
    int gid = blockIdx.x * 256 + threadIdx.x;
    const float4* p = (const float4*)g_Pp;
    const int STR = SEQ * EMB / 4;
    float4 s = p[gid];
#pragma unroll
    for (int z = 1; z < NSPLIT; z++) {
        float4 t = p[z * STR + gid];
        s.x += t.x; s.y += t.y; s.z += t.z; s.w += t.w;
    }
    ((float4*)out)[gid] = s;
}

// =======================================================================
extern "C" void kernel_launch(void* const* d_in, const int* in_sizes, int n_in,
                              void* d_out, int out_size)
{
    (void)in_sizes; (void)n_in; (void)out_size;
    const float* x    = (const float*)d_in[0];
    const float* Wq   = (const float*)d_in[1];
    const float* bq   = (const float*)d_in[2];
    const float* Wk   = (const float*)d_in[3];
    const float* bk   = (const float*)d_in[4];
    const float* Wv   = (const float*)d_in[5];
    const float* bv   = (const float*)d_in[6];
    const float* proj = (const float*)d_in[7];
    float* out = (float*)d_out;

    cudaFuncSetAttribute(gemm_qkv_mma,  cudaFuncAttributeMaxDynamicSharedMemorySize, QKV_SMEM3);
    cudaFuncSetAttribute(attn_mma,      cudaFuncAttributeMaxDynamicSharedMemorySize, ATT_SMEM);
    cudaFuncSetAttribute(gemm_proj_mma, cudaFuncAttributeMaxDynamicSharedMemorySize, PRJ_SMEM);

    conv_all<<<(NX + NW + NP) / 1024, 256>>>(x, Wq, Wk, Wv, proj);

    gemm_qkv_mma<<<dim3(SEQ / 128, 48), 256, QKV_SMEM3>>>(bq, bk, bv);

    attn_mma<<<dim3(SEQ / 128, NH), 256, ATT_SMEM>>>();

    gemm_proj_mma<<<dim3(SEQ / 128, NSPLIT), 256, PRJ_SMEM>>>();
    proj_reduce<<<SEQ * EMB / 1024, 256>>>(out);
}